// round 16
// baseline (speedup 1.0000x reference)
#include <cuda_runtime.h>
#include <cuda_fp16.h>
#include <math.h>

#define N_NODES 50000
#define N_EDGES 800000
#define F_DIM   128
#define OUT_DIM 256
#define NBLK    196   // ceil(50000/256); also persistent-kernel grid size
#define MCHUNK  25000 // GEMM2/agg2 pipeline chunk

// ---------------- device scratch (no allocations allowed) ----------------
__device__ float    g_bufA[(size_t)N_NODES * F_DIM];   // reused as fp16
__device__ float    g_bufB[(size_t)N_NODES * F_DIM];
__device__ int      g_cnt[N_NODES];
__device__ int      g_rowptr[N_NODES + 1];
__device__ int      g_cursor[N_NODES];
__device__ int      g_col[N_EDGES];
__device__ float    g_dinv[N_NODES];
__device__ float    g_logits[N_NODES];
__device__ int      g_part[NBLK];
__device__ unsigned g_max_enc;
__device__ float    g_wsum;
__device__ float    g_gacc[OUT_DIM];
__device__ int      g_is64;
// software grid barrier state (generation monotone across replays)
__device__ unsigned g_barcnt;
__device__ volatile unsigned g_bargen;

// ---------------- helpers ----------------
__device__ __forceinline__ int edge_src(const void* ei, int e) {
    return g_is64 ? (int)((const long long*)ei)[e] : ((const int*)ei)[e];
}
__device__ __forceinline__ int edge_dst(const void* ei, int e) {
    return g_is64 ? (int)((const long long*)ei)[(size_t)N_EDGES + e]
                  : ((const int*)ei)[(size_t)N_EDGES + e];
}
__device__ __forceinline__ unsigned f2tf(float f) {
    unsigned r;
    asm("cvt.rna.tf32.f32 %0, %1;" : "=r"(r) : "f"(f));
    return r;
}
__device__ __forceinline__ void mma_tf32(float& c0, float& c1, float& c2, float& c3,
                                         unsigned a0, unsigned a1, unsigned a2, unsigned a3,
                                         unsigned b0, unsigned b1) {
    asm volatile("mma.sync.aligned.m16n8k8.row.col.f32.tf32.tf32.f32 "
                 "{%0,%1,%2,%3}, {%4,%5,%6,%7}, {%8,%9}, {%0,%1,%2,%3};"
                 : "+f"(c0), "+f"(c1), "+f"(c2), "+f"(c3)
                 : "r"(a0), "r"(a1), "r"(a2), "r"(a3), "r"(b0), "r"(b1));
}

// device-wide barrier for persistent kernels (all blocks must be resident;
// grid=196 blocks x 256 thr needs only 25 SMs at 8 blocks/SM -> guaranteed)
__device__ __forceinline__ void grid_barrier(unsigned nb) {
    __syncthreads();
    if (threadIdx.x == 0) {
        unsigned my = g_bargen;
        __threadfence();
        unsigned arrived = atomicAdd(&g_barcnt, 1u) + 1u;
        if (arrived == nb) {
            g_barcnt = 0u;
            __threadfence();
            g_bargen = my + 1u;
        } else {
            while (g_bargen == my) { }
        }
    }
    __syncthreads();
}

// exclusive block scan of 256 ints, 2 syncthreads (warp shuffles + 8-wide fixup)
__device__ __forceinline__ int blockscan256_excl(int v, int t, int* wsum) {
    int lane = t & 31, w = t >> 5;
    int incl = v;
    #pragma unroll
    for (int off = 1; off < 32; off <<= 1) {
        int u = __shfl_up_sync(0xffffffffu, incl, off);
        if (lane >= off) incl += u;
    }
    if (lane == 31) wsum[w] = incl;
    __syncthreads();
    if (w == 0 && lane < 8) {
        int s = wsum[lane];
        #pragma unroll
        for (int off = 1; off < 8; off <<= 1) {
            int u = __shfl_up_sync(0xffu, s, off);
            if (lane >= off) s += u;
        }
        wsum[lane] = s;  // inclusive
    }
    __syncthreads();
    int base = (w > 0) ? wsum[w - 1] : 0;
    return base + incl - v;
}

// ---------------- CSR megakernel: init/count/scan/fill in ONE launch -----------
__global__ __launch_bounds__(256, 8) void k_csr(const void* __restrict__ ei) {
    __shared__ int ws1[8];
    __shared__ int ws2[8];
    __shared__ int baseSh[256];
    int t = threadIdx.x;
    int b = blockIdx.x;
    int i = b * 256 + t;
    const int NT = NBLK * 256;       // total threads
    int gtid = b * 256 + t;

    // phase A: zero cnt/cursor/logits rows; block 0 scalars + dtype detect
    if (i < N_NODES) { g_cnt[i] = 0; g_cursor[i] = 0; g_logits[i] = 0.f; }
    if (b == 0) {
        g_gacc[t] = 0.f;
        if (t == 0) {
            g_wsum = 0.f; g_max_enc = 0u;
            g_rowptr[N_NODES] = N_EDGES;
            const int* p = (const int*)ei;
            int ornz = 0;
            #pragma unroll 8
            for (int k = 0; k < 256; k++) ornz |= p[2 * k + 1];
            g_is64 = (ornz == 0) ? 1 : 0;
        }
    }
    grid_barrier(NBLK);

    // phase B: degree histogram (grid-stride over edges)
    for (int e = gtid; e < N_EDGES; e += NT)
        atomicAdd(&g_cnt[edge_dst(ei, e)], 1);
    grid_barrier(NBLK);

    // phase C: per-block sums + dinv
    int v = (i < N_NODES) ? g_cnt[i] : 0;
    if (i < N_NODES) g_dinv[i] = rsqrtf((float)(v + 1));  // +1 self-loop
    {
        int s = v;
        #pragma unroll
        for (int off = 16; off; off >>= 1) s += __shfl_xor_sync(0xffffffffu, s, off);
        if ((t & 31) == 0) ws1[t >> 5] = s;
        __syncthreads();
        if (t == 0) {
            int tot = 0;
            #pragma unroll
            for (int q = 0; q < 8; q++) tot += ws1[q];
            g_part[b] = tot;
        }
    }
    grid_barrier(NBLK);

    // phase D: rowptr (redundant scan of partials per block + local scan)
    {
        int pv = (t < NBLK) ? g_part[t] : 0;
        int pex = blockscan256_excl(pv, t, ws1);
        baseSh[t] = pex;
        __syncthreads();
        int vex = blockscan256_excl(v, t, ws2);
        if (i < N_NODES) g_rowptr[i] = baseSh[b] + vex;
    }
    grid_barrier(NBLK);

    // phase E: fill columns
    for (int e = gtid; e < N_EDGES; e += NT) {
        int s = edge_src(ei, e);
        int d = edge_dst(ei, e);
        int pos = g_rowptr[d] + atomicAdd(&g_cursor[d], 1);
        g_col[pos] = s;
    }
}

// ---------------- GCN aggregation (fp16): 2 nodes/warp, 16 lanes x uint4 -------
__global__ void k_agg_h(const __half* __restrict__ in, __half* __restrict__ out,
                        const float* __restrict__ bias,
                        int node0, int nnodes) {
    int tid = blockIdx.x * blockDim.x + threadIdx.x;
    int node = node0 + (tid >> 4);            // 16 lanes per node
    if (node >= node0 + nnodes) return;
    int l16 = threadIdx.x & 15;
    const uint4* inv = reinterpret_cast<const uint4*>(in);  // row = 16 uint4
    float di = __ldg(&g_dinv[node]);
    uint4 raw = inv[(size_t)node * 16 + l16];
    float sw = di * di;
    float2 c0 = __half22float2(*reinterpret_cast<__half2*>(&raw.x));
    float2 c1 = __half22float2(*reinterpret_cast<__half2*>(&raw.y));
    float2 c2 = __half22float2(*reinterpret_cast<__half2*>(&raw.z));
    float2 c3 = __half22float2(*reinterpret_cast<__half2*>(&raw.w));
    float a0 = c0.x * sw, a1 = c0.y * sw, a2 = c1.x * sw, a3 = c1.y * sw;
    float a4 = c2.x * sw, a5 = c2.y * sw, a6 = c3.x * sw, a7 = c3.y * sw;
    int p = g_rowptr[node], end = g_rowptr[node + 1];
    for (; p + 8 <= end; p += 8) {
        int s[8]; uint4 rr[8]; float w[8];
        #pragma unroll
        for (int q = 0; q < 8; q++) s[q] = __ldg(&g_col[p + q]);
        #pragma unroll
        for (int q = 0; q < 8; q++) rr[q] = inv[(size_t)s[q] * 16 + l16];
        #pragma unroll
        for (int q = 0; q < 8; q++) w[q] = __ldg(&g_dinv[s[q]]) * di;
        #pragma unroll
        for (int q = 0; q < 8; q++) {
            float2 u0 = __half22float2(*reinterpret_cast<__half2*>(&rr[q].x));
            float2 u1 = __half22float2(*reinterpret_cast<__half2*>(&rr[q].y));
            float2 u2 = __half22float2(*reinterpret_cast<__half2*>(&rr[q].z));
            float2 u3 = __half22float2(*reinterpret_cast<__half2*>(&rr[q].w));
            a0 = fmaf(u0.x, w[q], a0); a1 = fmaf(u0.y, w[q], a1);
            a2 = fmaf(u1.x, w[q], a2); a3 = fmaf(u1.y, w[q], a3);
            a4 = fmaf(u2.x, w[q], a4); a5 = fmaf(u2.y, w[q], a5);
            a6 = fmaf(u3.x, w[q], a6); a7 = fmaf(u3.y, w[q], a7);
        }
    }
    for (; p < end; ++p) {
        int s = __ldg(&g_col[p]);
        float w = __ldg(&g_dinv[s]) * di;
        uint4 rr = inv[(size_t)s * 16 + l16];
        float2 u0 = __half22float2(*reinterpret_cast<__half2*>(&rr.x));
        float2 u1 = __half22float2(*reinterpret_cast<__half2*>(&rr.y));
        float2 u2 = __half22float2(*reinterpret_cast<__half2*>(&rr.z));
        float2 u3 = __half22float2(*reinterpret_cast<__half2*>(&rr.w));
        a0 = fmaf(u0.x, w, a0); a1 = fmaf(u0.y, w, a1);
        a2 = fmaf(u1.x, w, a2); a3 = fmaf(u1.y, w, a3);
        a4 = fmaf(u2.x, w, a4); a5 = fmaf(u2.y, w, a5);
        a6 = fmaf(u3.x, w, a6); a7 = fmaf(u3.y, w, a7);
    }
    if (bias) {
        const float4* bp = reinterpret_cast<const float4*>(bias) + l16 * 2;
        float4 bv0 = bp[0], bv1 = bp[1];
        a0 = fmaxf(a0 + bv0.x, 0.f); a1 = fmaxf(a1 + bv0.y, 0.f);
        a2 = fmaxf(a2 + bv0.z, 0.f); a3 = fmaxf(a3 + bv0.w, 0.f);
        a4 = fmaxf(a4 + bv1.x, 0.f); a5 = fmaxf(a5 + bv1.y, 0.f);
        a6 = fmaxf(a6 + bv1.z, 0.f); a7 = fmaxf(a7 + bv1.w, 0.f);
    }
    __half2 o0 = __floats2half2_rn(a0, a1), o1 = __floats2half2_rn(a2, a3);
    __half2 o2 = __floats2half2_rn(a4, a5), o3 = __floats2half2_rn(a6, a7);
    uint4 st;
    st.x = *reinterpret_cast<unsigned*>(&o0);
    st.y = *reinterpret_cast<unsigned*>(&o1);
    st.z = *reinterpret_cast<unsigned*>(&o2);
    st.w = *reinterpret_cast<unsigned*>(&o3);
    reinterpret_cast<uint4*>(out)[(size_t)node * 16 + l16] = st;
}

// ---------------- TF32 tensor-core GEMM (rowoff for global logit index) --------
#define AS_STRIDE 20
#define BS_STRIDE 136
template<bool AHALF, bool OUTHALF>
__global__ __launch_bounds__(256, 2) void k_gemm(
    const void* __restrict__ Avoid, const float* __restrict__ B,
    const float* __restrict__ bias, void* __restrict__ Cvoid, int M, int N,
    const float* __restrict__ Wa, int rowoff) {
    const int K = 128;
    __shared__ unsigned As[2][128 * AS_STRIDE];
    __shared__ unsigned Bs[2][16 * BS_STRIDE];

    int t = threadIdx.x;
    int lane = t & 31;
    int warp = t >> 5;
    int g = lane >> 2, tig = lane & 3;
    int row0 = blockIdx.x * 128;
    int col0 = blockIdx.y * 128;
    int warpM = warp & 3, warpN = warp >> 2;
    int rowBase = warpM * 32;
    int colBase = warpN * 64;

    int arow = t >> 1;
    int ahalf = (t & 1) * 8;
    int garow = row0 + arow;
    bool aval = garow < M;
    const float*  Apf = (const float*)Avoid + (size_t)garow * K + ahalf;
    const __half* Aph = (const __half*)Avoid + (size_t)garow * K + ahalf;
    int brow = t >> 4;
    int bcol = (t & 15) * 8;
    const float* Bp = B + (size_t)brow * N + col0 + bcol;

    float4 aR0, aR1;
    uint4 aRh;
    if (AHALF) {
        aRh = aval ? *reinterpret_cast<const uint4*>(Aph) : make_uint4(0, 0, 0, 0);
    } else {
        aR0 = aval ? *reinterpret_cast<const float4*>(Apf)     : make_float4(0, 0, 0, 0);
        aR1 = aval ? *reinterpret_cast<const float4*>(Apf + 4) : make_float4(0, 0, 0, 0);
    }
    float4 bR0 = *reinterpret_cast<const float4*>(Bp);
    float4 bR1 = *reinterpret_cast<const float4*>(Bp + 4);

    float c[2][8][4];
    #pragma unroll
    for (int i = 0; i < 2; i++)
        #pragma unroll
        for (int j = 0; j < 8; j++)
            #pragma unroll
            for (int q = 0; q < 4; q++) c[i][j][q] = 0.f;

    int buf = 0;
    for (int kt = 0; kt < K; kt += 16) {
        unsigned* as = &As[buf][arow * AS_STRIDE + ahalf];
        if (AHALF) {
            #pragma unroll
            for (int q = 0; q < 4; q++) {
                unsigned rw = (q == 0) ? aRh.x : (q == 1) ? aRh.y : (q == 2) ? aRh.z : aRh.w;
                float2 f = __half22float2(*reinterpret_cast<__half2*>(&rw));
                as[2 * q]     = __float_as_uint(f.x);
                as[2 * q + 1] = __float_as_uint(f.y);
            }
        } else {
            as[0] = f2tf(aR0.x); as[1] = f2tf(aR0.y); as[2] = f2tf(aR0.z); as[3] = f2tf(aR0.w);
            as[4] = f2tf(aR1.x); as[5] = f2tf(aR1.y); as[6] = f2tf(aR1.z); as[7] = f2tf(aR1.w);
        }
        unsigned* bs = &Bs[buf][brow * BS_STRIDE + bcol];
        bs[0] = f2tf(bR0.x); bs[1] = f2tf(bR0.y); bs[2] = f2tf(bR0.z); bs[3] = f2tf(bR0.w);
        bs[4] = f2tf(bR1.x); bs[5] = f2tf(bR1.y); bs[6] = f2tf(bR1.z); bs[7] = f2tf(bR1.w);
        __syncthreads();
        if (kt + 16 < K) {
            if (AHALF) {
                aRh = aval ? *reinterpret_cast<const uint4*>(Aph + kt + 16)
                           : make_uint4(0, 0, 0, 0);
            } else {
                aR0 = aval ? *reinterpret_cast<const float4*>(Apf + kt + 16)
                           : make_float4(0, 0, 0, 0);
                aR1 = aval ? *reinterpret_cast<const float4*>(Apf + kt + 16 + 4)
                           : make_float4(0, 0, 0, 0);
            }
            bR0 = *reinterpret_cast<const float4*>(Bp + (size_t)(kt + 16) * N);
            bR1 = *reinterpret_cast<const float4*>(Bp + (size_t)(kt + 16) * N + 4);
        }
        #pragma unroll
        for (int ks = 0; ks < 2; ks++) {
            int k0 = ks * 8;
            unsigned a[2][4];
            #pragma unroll
            for (int mt = 0; mt < 2; mt++) {
                int r = rowBase + mt * 16 + g;
                a[mt][0] = As[buf][(r    ) * AS_STRIDE + k0 + tig];
                a[mt][1] = As[buf][(r + 8) * AS_STRIDE + k0 + tig];
                a[mt][2] = As[buf][(r    ) * AS_STRIDE + k0 + tig + 4];
                a[mt][3] = As[buf][(r + 8) * AS_STRIDE + k0 + tig + 4];
            }
            #pragma unroll
            for (int nt = 0; nt < 8; nt++) {
                int n = colBase + nt * 8 + g;
                unsigned b0 = Bs[buf][(k0 + tig    ) * BS_STRIDE + n];
                unsigned b1 = Bs[buf][(k0 + tig + 4) * BS_STRIDE + n];
                #pragma unroll
                for (int mt = 0; mt < 2; mt++)
                    mma_tf32(c[mt][nt][0], c[mt][nt][1], c[mt][nt][2], c[mt][nt][3],
                             a[mt][0], a[mt][1], a[mt][2], a[mt][3], b0, b1);
            }
        }
        buf ^= 1;
    }

    float*  Cf = (float*)Cvoid;
    __half* Ch = (__half*)Cvoid;
    #pragma unroll
    for (int mt = 0; mt < 2; mt++) {
        int r0 = row0 + rowBase + mt * 16 + g;   // chunk-local; and r0+8
        float p0 = 0.f, p1 = 0.f;
        #pragma unroll
        for (int nt = 0; nt < 8; nt++) {
            int col = col0 + colBase + nt * 8 + tig * 2;
            float o0 = c[mt][nt][0], o1 = c[mt][nt][1];
            float o2 = c[mt][nt][2], o3 = c[mt][nt][3];
            if (bias) {
                float bb0 = bias[col], bb1 = bias[col + 1];
                o0 = fmaxf(o0 + bb0, 0.f); o1 = fmaxf(o1 + bb1, 0.f);
                o2 = fmaxf(o2 + bb0, 0.f); o3 = fmaxf(o3 + bb1, 0.f);
            }
            if (OUTHALF) {
                __half2 ho = __floats2half2_rn(o0, o1);
                __half2 hp = __floats2half2_rn(o2, o3);
                if (r0 < M)
                    *reinterpret_cast<__half2*>(&Ch[(size_t)r0 * N + col]) = ho;
                if (r0 + 8 < M)
                    *reinterpret_cast<__half2*>(&Ch[(size_t)(r0 + 8) * N + col]) = hp;
            } else {
                if (r0 < M)
                    *reinterpret_cast<float2*>(&Cf[(size_t)r0 * N + col]) = make_float2(o0, o1);
                if (r0 + 8 < M)
                    *reinterpret_cast<float2*>(&Cf[(size_t)(r0 + 8) * N + col]) = make_float2(o2, o3);
            }
            if (Wa) {
                float w0 = Wa[col], w1 = Wa[col + 1];
                p0 = fmaf(o0, w0, fmaf(o1, w1, p0));
                p1 = fmaf(o2, w0, fmaf(o3, w1, p1));
            }
        }
        if (Wa) {
            p0 += __shfl_xor_sync(0xffffffffu, p0, 1);
            p0 += __shfl_xor_sync(0xffffffffu, p0, 2);
            p1 += __shfl_xor_sync(0xffffffffu, p1, 1);
            p1 += __shfl_xor_sync(0xffffffffu, p1, 2);
            if (tig == 0) {
                if (r0 < M)     atomicAdd(&g_logits[rowoff + r0], p0);
                if (r0 + 8 < M) atomicAdd(&g_logits[rowoff + r0 + 8], p1);
            }
        }
    }
}

// ---------------- fused softmax tail: max + exp/pool/wsum + finish -------------
__global__ __launch_bounds__(256, 8) void k_softpool(const float* __restrict__ h2,
                                                     float* __restrict__ out_tail) {
    __shared__ float wsm[256];
    int t = threadIdx.x;
    int r0 = blockIdx.x * 256;
    int r = r0 + t;
    // phase 1: global max (order-preserving encode)
    float logit = (r < N_NODES) ? g_logits[r] : -3.4e38f;
    {
        unsigned bbits = __float_as_uint(logit);
        unsigned u = (bbits & 0x80000000u) ? ~bbits : (bbits | 0x80000000u);
        #pragma unroll
        for (int off = 16; off; off >>= 1) u = max(u, __shfl_xor_sync(0xffffffffu, u, off));
        if ((t & 31) == 0) atomicMax(&g_max_enc, u);
    }
    grid_barrier(NBLK);
    // phase 2: exp + wsum + weighted feature sum
    unsigned ue = g_max_enc;
    float m = (ue & 0x80000000u) ? __uint_as_float(ue & 0x7FFFFFFFu) : __uint_as_float(~ue);
    float w = (r < N_NODES) ? expf(logit - m) : 0.f;
    wsm[t] = w;
    float ws = w;
    #pragma unroll
    for (int off = 16; off; off >>= 1) ws += __shfl_xor_sync(0xffffffffu, ws, off);
    __syncthreads();
    if ((t & 31) == 0) atomicAdd(&g_wsum, ws);
    int rend = min(r0 + 256, N_NODES);
    float acc = 0.f;
    for (int rr = r0; rr < rend; rr++)
        acc = fmaf(h2[(size_t)rr * OUT_DIM + t], wsm[rr - r0], acc);
    atomicAdd(&g_gacc[t], acc);
    grid_barrier(NBLK);
    // phase 3: block 0 writes the normalized graph embedding
    if (blockIdx.x == 0)
        out_tail[t] = g_gacc[t] / g_wsum;
}

// ---------------- launch ----------------
extern "C" void kernel_launch(void* const* d_in, const int* in_sizes, int n_in,
                              void* d_out, int out_size) {
    const float* x  = (const float*)d_in[0];
    const void*  ei = d_in[1];
    const float* W1 = (const float*)d_in[2];
    const float* b1 = (const float*)d_in[3];
    const float* W2 = (const float*)d_in[4];
    const float* b2 = (const float*)d_in[5];
    const float* Wa = (const float*)d_in[6];
    float* out = (float*)d_out;

    float *bufA, *bufB;
    cudaGetSymbolAddress((void**)&bufA, g_bufA);
    cudaGetSymbolAddress((void**)&bufB, g_bufB);
    __half* hA = (__half*)bufA;
    __half* hB = (__half*)bufB;

    static cudaStream_t s2 = nullptr;
    static cudaEvent_t evFork = nullptr, evJoin = nullptr;
    static cudaEvent_t evA0 = nullptr, evA1 = nullptr, evG2 = nullptr;
    if (!s2) {
        cudaStreamCreateWithFlags(&s2, cudaStreamNonBlocking);
        cudaEventCreateWithFlags(&evFork, cudaEventDisableTiming);
        cudaEventCreateWithFlags(&evJoin, cudaEventDisableTiming);
        cudaEventCreateWithFlags(&evA0, cudaEventDisableTiming);
        cudaEventCreateWithFlags(&evA1, cudaEventDisableTiming);
        cudaEventCreateWithFlags(&evG2, cudaEventDisableTiming);
    }

    const int AGG_TPB = 256;                 // 16 nodes per block
    const int aggBlocksFull  = (N_NODES * 16 + AGG_TPB - 1) / AGG_TPB;
    const int aggBlocksChunk = (MCHUNK * 16 + AGG_TPB - 1) / AGG_TPB;

    // fork: CSR megakernel on s2, GEMM1 (x@W1 -> fp16) on main stream
    cudaEventRecord(evFork, 0);
    cudaStreamWaitEvent(s2, evFork, 0);

    k_csr<<<NBLK, 256, 0, s2>>>(ei);
    cudaEventRecord(evJoin, s2);

    {   // GEMM1 raw: hB = fp16(x @ W1)   (layer1 re-associated: relu(Agg(xW1)+b1))
        dim3 grid((N_NODES + 127) / 128, F_DIM / 128);
        k_gemm<false, true><<<grid, 256>>>(x, W1, nullptr, hB, N_NODES, F_DIM, nullptr, 0);
    }
    cudaStreamWaitEvent(0, evJoin, 0);

    // layer 1 aggregation with fused bias+relu: hA = h1 (fp16)
    k_agg_h<<<aggBlocksFull, AGG_TPB>>>(hB, hA, b1, 0, N_NODES);

    // layer 2 pipelined: agg2 chunk c on main, GEMM2 chunk c on s2
    dim3 grid2((MCHUNK + 127) / 128, OUT_DIM / 128);
    k_agg_h<<<aggBlocksChunk, AGG_TPB>>>(hA, hB, nullptr, 0, MCHUNK);
    cudaEventRecord(evA0, 0);
    k_agg_h<<<aggBlocksChunk, AGG_TPB>>>(hA, hB, nullptr, MCHUNK, N_NODES - MCHUNK);
    cudaEventRecord(evA1, 0);

    cudaStreamWaitEvent(s2, evA0, 0);
    k_gemm<true, false><<<grid2, 256, 0, s2>>>(
        hB, W2, b2, out, MCHUNK, OUT_DIM, Wa, 0);
    cudaStreamWaitEvent(s2, evA1, 0);
    k_gemm<true, false><<<grid2, 256, 0, s2>>>(
        hB + (size_t)MCHUNK * F_DIM, W2, b2, out + (size_t)MCHUNK * OUT_DIM,
        N_NODES - MCHUNK, OUT_DIM, Wa, MCHUNK);
    cudaEventRecord(evG2, s2);
    cudaStreamWaitEvent(0, evG2, 0);

    // fused softmax-weighted pooling (max + exp + pool + finish, one launch)
    k_softpool<<<NBLK, 256>>>(out, out + (size_t)N_NODES * OUT_DIM);
}